// round 4
// baseline (speedup 1.0000x reference)
#include <cuda_runtime.h>
#include <cuda_bf16.h>
#include <math.h>
#include <stdint.h>

#define BB 2
#define SS 2048
#define DD 1024
#define HH 16
#define DK 64
#define OUT_ELEMS (BB * SS * DD)
#define ATT_ELEMS ((long long)BB * HH * SS * (long long)SS)

// ---------------- scratch (allocation-free rule) ----------------
__device__ __align__(16) __nv_bfloat16 g_in_h[3][4194304];
__device__ __align__(16) __nv_bfloat16 g_in_l[3][4194304];
__device__ __align__(16) __nv_bfloat16 g_w_h[4][1048576];
__device__ __align__(16) __nv_bfloat16 g_w_l[4][1048576];
__device__ __align__(16) __nv_bfloat16 g_qh_h[4194304], g_qh_l[4194304];
__device__ __align__(16) __nv_bfloat16 g_kh_h[4194304], g_kh_l[4194304];
__device__ __align__(16) __nv_bfloat16 g_vt_h[4194304], g_vt_l[4194304];
__device__ __align__(16) __nv_bfloat16 g_ctx_h[4194304], g_ctx_l[4194304];

// ---------------- PTX helpers ----------------
__device__ __forceinline__ uint32_t smem_u32(const void* p) {
    return (uint32_t)__cvta_generic_to_shared(p);
}
__device__ __forceinline__ void ldm_x4(uint32_t* r, uint32_t addr) {
    asm volatile("ldmatrix.sync.aligned.m8n8.x4.shared.b16 {%0,%1,%2,%3}, [%4];\n"
                 : "=r"(r[0]), "=r"(r[1]), "=r"(r[2]), "=r"(r[3]) : "r"(addr));
}
__device__ __forceinline__ void mma16816(float* d, const uint32_t* a,
                                         uint32_t b0, uint32_t b1) {
    asm volatile(
        "mma.sync.aligned.m16n8k16.row.col.f32.bf16.bf16.f32 "
        "{%0,%1,%2,%3}, {%4,%5,%6,%7}, {%8,%9}, {%0,%1,%2,%3};\n"
        : "+f"(d[0]), "+f"(d[1]), "+f"(d[2]), "+f"(d[3])
        : "r"(a[0]), "r"(a[1]), "r"(a[2]), "r"(a[3]), "r"(b0), "r"(b1));
}
__device__ __forceinline__ void split2(float x, __nv_bfloat16& h, __nv_bfloat16& l) {
    h = __float2bfloat16(x);
    l = __float2bfloat16(x - __bfloat162float(h));
}
__device__ __forceinline__ void cp16(uint32_t dst, const void* src) {
    asm volatile("cp.async.cg.shared.global [%0], [%1], 16;\n" :: "r"(dst), "l"(src));
}
__device__ __forceinline__ void cp_commit() { asm volatile("cp.async.commit_group;\n"); }
__device__ __forceinline__ void cp_wait0() { asm volatile("cp.async.wait_group 0;\n" ::: "memory"); }
__device__ __forceinline__ void cp_wait1() { asm volatile("cp.async.wait_group 1;\n" ::: "memory"); }
__device__ __forceinline__ void cp_wait2() { asm volatile("cp.async.wait_group 2;\n" ::: "memory"); }

// ---------------------------------------------------------------------------
// Convert fp32 sources to bf16 hi/lo. grid = (4096, 7).
// ---------------------------------------------------------------------------
__global__ __launch_bounds__(256) void convert_all(
    const float* __restrict__ Q, const float* __restrict__ K,
    const float* __restrict__ V, const float* __restrict__ WQ,
    const float* __restrict__ WK, const float* __restrict__ WV,
    const float* __restrict__ WO)
{
    const int seg = blockIdx.y;
    const int nf4 = (seg < 3) ? (4194304 / 4) : (1048576 / 4);
    const int i = blockIdx.x * 256 + threadIdx.x;
    if (i >= nf4) return;
    const float* src;
    __nv_bfloat16 *dh, *dl;
    switch (seg) {
        case 0: src = Q;  dh = g_in_h[0]; dl = g_in_l[0]; break;
        case 1: src = K;  dh = g_in_h[1]; dl = g_in_l[1]; break;
        case 2: src = V;  dh = g_in_h[2]; dl = g_in_l[2]; break;
        case 3: src = WQ; dh = g_w_h[0];  dl = g_w_l[0];  break;
        case 4: src = WK; dh = g_w_h[1];  dl = g_w_l[1];  break;
        case 5: src = WV; dh = g_w_h[2];  dl = g_w_l[2];  break;
        default: src = WO; dh = g_w_h[3]; dl = g_w_l[3];  break;
    }
    float4 v = ((const float4*)src)[i];
    __nv_bfloat16 h0, l0, h1, l1, h2, l2, h3, l3;
    split2(v.x, h0, l0); split2(v.y, h1, l1);
    split2(v.z, h2, l2); split2(v.w, h3, l3);
    __nv_bfloat162 a, b;
    a.x = h0; a.y = h1; b.x = h2; b.y = h3;
    ((__nv_bfloat162*)dh)[i * 2 + 0] = a;
    ((__nv_bfloat162*)dh)[i * 2 + 1] = b;
    a.x = l0; a.y = l1; b.x = l2; b.y = l3;
    ((__nv_bfloat162*)dl)[i * 2 + 0] = a;
    ((__nv_bfloat162*)dl)[i * 2 + 1] = b;
}

// ---------------------------------------------------------------------------
// Projection GEMM: out = A @ B^T + bias. bf16 hi/lo preconverted.
// 4-stage cp.async ring, BK=16, block 128x128, 8 warps (4m x 2n).
// which=-1: z=blockIdx.z selects Q/K/V. which=3: O projection (fp32 out).
// ---------------------------------------------------------------------------
#define PPAD 24
#define PTILE (128 * PPAD)
#define PSTAGE (4 * PTILE)
#define PROJ_SMEM (4 * PSTAGE * (int)sizeof(__nv_bfloat16))  // 98304

__device__ __forceinline__ void proj_issue(
    __nv_bfloat16* ps, int stage,
    const __nv_bfloat16* Ah_, const __nv_bfloat16* Al_,
    const __nv_bfloat16* Bh_, const __nv_bfloat16* Bl_,
    int bm, int bn, int kt, int tid)
{
    __nv_bfloat16* base = ps + (stage & 3) * PSTAGE;
#pragma unroll
    for (int t = 0; t < 4; t++) {
        const int idx = tid + t * 256;
        const int arr = idx >> 8, row = (idx >> 1) & 127, ch = idx & 1;
        const __nv_bfloat16* g;
        if (arr == 0)      g = Ah_ + (size_t)(bm * 128 + row) * 1024 + kt + ch * 8;
        else if (arr == 1) g = Al_ + (size_t)(bm * 128 + row) * 1024 + kt + ch * 8;
        else if (arr == 2) g = Bh_ + (size_t)(bn * 128 + row) * 1024 + kt + ch * 8;
        else               g = Bl_ + (size_t)(bn * 128 + row) * 1024 + kt + ch * 8;
        cp16(smem_u32(base + arr * PTILE + row * PPAD + ch * 8), g);
    }
    cp_commit();
}

__global__ __launch_bounds__(256, 2) void proj_gemm(
    const __nv_bfloat16* __restrict__ inh, const __nv_bfloat16* __restrict__ inl,
    const __nv_bfloat16* __restrict__ wh, const __nv_bfloat16* __restrict__ wl,
    const __nv_bfloat16* __restrict__ cth, const __nv_bfloat16* __restrict__ ctl,
    const float* __restrict__ bQ, const float* __restrict__ bK,
    const float* __restrict__ bV, const float* __restrict__ bO,
    float* __restrict__ outO,
    __nv_bfloat16* __restrict__ qhh, __nv_bfloat16* __restrict__ qhl,
    __nv_bfloat16* __restrict__ khh, __nv_bfloat16* __restrict__ khl,
    __nv_bfloat16* __restrict__ vth, __nv_bfloat16* __restrict__ vtl,
    int which)
{
    extern __shared__ __nv_bfloat16 ps[];
    const int tid = threadIdx.x, lane = tid & 31, wid = tid >> 5;
    const int wm = wid >> 1, wn = wid & 1;
    const int bm = blockIdx.y, bn = blockIdx.x;
    const int z = (which >= 0) ? which : (int)blockIdx.z;

    const __nv_bfloat16 *Ah_, *Al_, *Bh_, *Bl_;
    const float* bias;
    __nv_bfloat16 *oh = nullptr, *ol = nullptr;
    int mode; float scale = 1.0f;
    if (z == 0) { Ah_ = inh; Al_ = inl; Bh_ = wh; Bl_ = wl; bias = bQ;
                  oh = qhh; ol = qhl; mode = 1;
                  scale = 0.125f * 1.4426950408889634f; }
    else if (z == 1) { Ah_ = inh + 4194304; Al_ = inl + 4194304;
                       Bh_ = wh + 1048576; Bl_ = wl + 1048576; bias = bK;
                       oh = khh; ol = khl; mode = 1; }
    else if (z == 2) { Ah_ = inh + 2 * 4194304; Al_ = inl + 2 * 4194304;
                       Bh_ = wh + 2 * 1048576; Bl_ = wl + 2 * 1048576; bias = bV;
                       oh = vth; ol = vtl; mode = 2; }
    else { Ah_ = cth; Al_ = ctl; Bh_ = wh + 3 * 1048576; Bl_ = wl + 3 * 1048576;
           bias = bO; mode = 0; }

    float acc[2][8][4];
#pragma unroll
    for (int m = 0; m < 2; m++)
#pragma unroll
        for (int n = 0; n < 8; n++)
#pragma unroll
            for (int k = 0; k < 4; k++) acc[m][n][k] = 0.0f;

    proj_issue(ps, 0, Ah_, Al_, Bh_, Bl_, bm, bn, 0, tid);
    proj_issue(ps, 1, Ah_, Al_, Bh_, Bl_, bm, bn, 16, tid);
    proj_issue(ps, 2, Ah_, Al_, Bh_, Bl_, bm, bn, 32, tid);

    for (int i = 0; i < 64; i++) {
        if (i <= 61) cp_wait2(); else if (i == 62) cp_wait1(); else cp_wait0();
        __syncthreads();
        __nv_bfloat16* Ah = ps + (i & 3) * PSTAGE;
        __nv_bfloat16* Al = Ah + PTILE;
        __nv_bfloat16* Bh = Al + PTILE;
        __nv_bfloat16* Bl = Bh + PTILE;

        uint32_t ah[2][4], al[2][4];
#pragma unroll
        for (int mt = 0; mt < 2; mt++) {
            const int r = wm * 32 + mt * 16 + (lane & 15);
            const int c = (lane >> 4) * 8;
            ldm_x4(ah[mt], smem_u32(&Ah[r * PPAD + c]));
            ldm_x4(al[mt], smem_u32(&Al[r * PPAD + c]));
        }
#pragma unroll
        for (int nt = 0; nt < 4; nt++) {
            uint32_t bh[4], bl[4];
            const int r = wn * 64 + nt * 16 + (lane & 15);
            const int c = (lane >> 4) * 8;
            ldm_x4(bh, smem_u32(&Bh[r * PPAD + c]));
            ldm_x4(bl, smem_u32(&Bl[r * PPAD + c]));
#pragma unroll
            for (int mt = 0; mt < 2; mt++) {
                mma16816(acc[mt][nt * 2 + 0], ah[mt], bh[0], bh[2]);
                mma16816(acc[mt][nt * 2 + 1], ah[mt], bh[1], bh[3]);
                mma16816(acc[mt][nt * 2 + 0], ah[mt], bl[0], bl[2]);
                mma16816(acc[mt][nt * 2 + 1], ah[mt], bl[1], bl[3]);
                mma16816(acc[mt][nt * 2 + 0], al[mt], bh[0], bh[2]);
                mma16816(acc[mt][nt * 2 + 1], al[mt], bh[1], bh[3]);
            }
        }
        __syncthreads();
        if (i + 3 < 64)
            proj_issue(ps, i + 3, Ah_, Al_, Bh_, Bl_, bm, bn, (i + 3) * 16, tid);
    }

#pragma unroll
    for (int mt = 0; mt < 2; mt++) {
#pragma unroll
        for (int n8 = 0; n8 < 8; n8++) {
            const int r0 = bm * 128 + wm * 32 + mt * 16 + (lane >> 2);
            const int c  = bn * 128 + wn * 64 + n8 * 8 + (lane & 3) * 2;
            const float b0 = bias[c], b1 = bias[c + 1];
#pragma unroll
            for (int half = 0; half < 2; half++) {
                const int r = r0 + half * 8;
                const float v0 = (acc[mt][n8][half * 2 + 0] + b0) * scale;
                const float v1 = (acc[mt][n8][half * 2 + 1] + b1) * scale;
                if (mode == 0) {
                    *(float2*)&outO[(size_t)r * DD + c] = make_float2(v0, v1);
                } else {
                    const int bb = r >> 11, sidx = r & 2047;
                    const int hh = c >> 6, dk = c & 63;
                    __nv_bfloat16 h0, l0, h1, l1;
                    split2(v0, h0, l0); split2(v1, h1, l1);
                    if (mode == 1) {
                        const size_t a = ((size_t)(bb * HH + hh) * SS + sidx) * DK + dk;
                        __nv_bfloat162 th, tl;
                        th.x = h0; th.y = h1; tl.x = l0; tl.y = l1;
                        *(__nv_bfloat162*)&oh[a] = th;
                        *(__nv_bfloat162*)&ol[a] = tl;
                    } else {
                        const size_t a = ((size_t)(bb * HH + hh) * DK + dk) * SS + sidx;
                        oh[a] = h0; ol[a] = l0;
                        oh[a + SS] = h1; ol[a + SS] = l1;
                    }
                }
            }
        }
    }
}

// ---------------------------------------------------------------------------
// Attention, two-pass per CTA (no rescale kernel):
//   pass A: S = Q K^T, exp2, accumulate row sums l   (K tiles only)
//   pass B: recompute S, p = exp2(s)*invl, write normalized attn (write-only),
//           PV mma; epilogue zero-fills upper-triangle columns.
// Q pre-scaled by 0.125*log2e. V transposed [bh][dk][s]. 2-stage cp.async.
// 256 thr, 8 warps (4 q x 2 col), 64x64 tiles. q-tiles scheduled longest-first.
// ---------------------------------------------------------------------------
#define APAD 72
#define ATILE (64 * APAD)
#define ATT_SMEM (10 * ATILE * (int)sizeof(__nv_bfloat16) + 512)

__device__ __forceinline__ void attn_issueKV(
    __nv_bfloat16* sm, int stage,
    const __nv_bfloat16* Kh_, const __nv_bfloat16* Kl_,
    const __nv_bfloat16* Vth_, const __nv_bfloat16* Vtl_,
    int bh, int k0, int tid)
{
    __nv_bfloat16* base = sm + stage * 4 * ATILE;
#pragma unroll
    for (int t = 0; t < 8; t++) {
        const int idx = tid + t * 256;
        const int arr = idx >> 9, row = (idx >> 3) & 63, ch = idx & 7;
        const __nv_bfloat16* g;
        if (arr == 0)      g = Kh_ + ((size_t)bh * SS + k0 + row) * DK + ch * 8;
        else if (arr == 1) g = Kl_ + ((size_t)bh * SS + k0 + row) * DK + ch * 8;
        else if (arr == 2) g = Vth_ + ((size_t)bh * DK + row) * SS + k0 + ch * 8;
        else               g = Vtl_ + ((size_t)bh * DK + row) * SS + k0 + ch * 8;
        cp16(smem_u32(base + arr * ATILE + row * APAD + ch * 8), g);
    }
    cp_commit();
}

__device__ __forceinline__ void attn_issueK(
    __nv_bfloat16* sm, int stage,
    const __nv_bfloat16* Kh_, const __nv_bfloat16* Kl_,
    int bh, int k0, int tid)
{
    __nv_bfloat16* base = sm + stage * 4 * ATILE;
#pragma unroll
    for (int t = 0; t < 4; t++) {
        const int idx = tid + t * 256;
        const int arr = idx >> 9, row = (idx >> 3) & 63, ch = idx & 7;
        const __nv_bfloat16* g = (arr ? Kl_ : Kh_) +
            ((size_t)bh * SS + k0 + row) * DK + ch * 8;
        cp16(smem_u32(base + arr * ATILE + row * APAD + ch * 8), g);
    }
    cp_commit();
}

__global__ __launch_bounds__(256, 2) void attn_mma(
    const __nv_bfloat16* __restrict__ Qh_, const __nv_bfloat16* __restrict__ Ql_,
    const __nv_bfloat16* __restrict__ Kh_, const __nv_bfloat16* __restrict__ Kl_,
    const __nv_bfloat16* __restrict__ Vth_, const __nv_bfloat16* __restrict__ Vtl_,
    __nv_bfloat16* __restrict__ ctxh, __nv_bfloat16* __restrict__ ctxl,
    float* __restrict__ attn_out, int write_attn)
{
    extern __shared__ __nv_bfloat16 sm[];
    __nv_bfloat16* Ph = sm + 8 * ATILE;
    __nv_bfloat16* Pl = sm + 9 * ATILE;
    float* l_sm = (float*)(sm + 10 * ATILE);  // [2][64]

    const int tid = threadIdx.x, lane = tid & 31, wid = tid >> 5;
    const int wm = wid >> 1, wn = wid & 1;
    const int b = blockIdx.z, h = blockIdx.y, bh = b * HH + h;
    const int q0 = ((int)gridDim.x - 1 - (int)blockIdx.x) * 64;  // longest first

    // ---- prologue: Q tile -> Ph/Pl, K tile 0 -> stage 0 ----
#pragma unroll
    for (int t = 0; t < 4; t++) {
        const int idx = tid + t * 256;
        const int arr = idx >> 9, row = (idx >> 3) & 63, ch = idx & 7;
        const __nv_bfloat16* g =
            (arr ? Ql_ : Qh_) + ((size_t)bh * SS + q0 + row) * DK + ch * 8;
        cp16(smem_u32((arr ? Pl : Ph) + row * APAD + ch * 8), g);
    }
    cp_commit();
    attn_issueK(sm, 0, Kh_, Kl_, bh, 0, tid);
    cp_wait0();
    __syncthreads();

    uint32_t qfh[4][4], qfl[4][4];
#pragma unroll
    for (int kk = 0; kk < 4; kk++) {
        const int r = wm * 16 + (lane & 15);
        const int c = kk * 16 + (lane >> 4) * 8;
        ldm_x4(qfh[kk], smem_u32(&Ph[r * APAD + c]));
        ldm_x4(qfl[kk], smem_u32(&Pl[r * APAD + c]));
    }

    const int qr0 = q0 + wm * 16 + (lane >> 2);
    float lacc0 = 0.0f, lacc1 = 0.0f;

    // ================= PASS A: row sums only =================
    for (int k0 = 0; k0 <= q0; k0 += 64) {
        const int s = (k0 >> 6) & 1;
        cp_wait0();
        __syncthreads();
        if (k0 + 64 <= q0)
            attn_issueK(sm, s ^ 1, Kh_, Kl_, bh, k0 + 64, tid);

        __nv_bfloat16* Kh = sm + s * 4 * ATILE;
        __nv_bfloat16* Kl = Kh + ATILE;

        float sa[4][4];
#pragma unroll
        for (int f = 0; f < 4; f++)
#pragma unroll
            for (int k = 0; k < 4; k++) sa[f][k] = 0.0f;

#pragma unroll
        for (int kk = 0; kk < 4; kk++) {
#pragma unroll
            for (int nt = 0; nt < 2; nt++) {
                uint32_t bhf[4], blf[4];
                const int r = wn * 32 + nt * 16 + (lane & 15);
                const int c = kk * 16 + (lane >> 4) * 8;
                ldm_x4(bhf, smem_u32(&Kh[r * APAD + c]));
                ldm_x4(blf, smem_u32(&Kl[r * APAD + c]));
                mma16816(sa[nt * 2 + 0], qfh[kk], bhf[0], bhf[2]);
                mma16816(sa[nt * 2 + 1], qfh[kk], bhf[1], bhf[3]);
                mma16816(sa[nt * 2 + 0], qfh[kk], blf[0], blf[2]);
                mma16816(sa[nt * 2 + 1], qfh[kk], blf[1], blf[3]);
                mma16816(sa[nt * 2 + 0], qfl[kk], bhf[0], bhf[2]);
                mma16816(sa[nt * 2 + 1], qfl[kk], bhf[1], bhf[3]);
            }
        }

        const bool diag = (k0 == q0);
#pragma unroll
        for (int f = 0; f < 4; f++) {
            const int jc = k0 + wn * 32 + f * 8 + (lane & 3) * 2;
#pragma unroll
            for (int half = 0; half < 2; half++) {
                const int qr = qr0 + half * 8;
                float p0 = exp2f(sa[f][half * 2 + 0]);
                float p1 = exp2f(sa[f][half * 2 + 1]);
                if (diag) {
                    if (jc + 0 > qr) p0 = 0.0f;
                    if (jc + 1 > qr) p1 = 0.0f;
                }
                if (half == 0) lacc0 += p0 + p1; else lacc1 += p0 + p1;
            }
        }
    }

    // row-sum reduction (4 lanes per row, then 2 column-warps via smem)
    lacc0 += __shfl_xor_sync(0xffffffffu, lacc0, 1);
    lacc0 += __shfl_xor_sync(0xffffffffu, lacc0, 2);
    lacc1 += __shfl_xor_sync(0xffffffffu, lacc1, 1);
    lacc1 += __shfl_xor_sync(0xffffffffu, lacc1, 2);
    if ((lane & 3) == 0) {
        l_sm[wn * 64 + wm * 16 + (lane >> 2) + 0] = lacc0;
        l_sm[wn * 64 + wm * 16 + (lane >> 2) + 8] = lacc1;
    }
    cp_wait0();
    __syncthreads();
    const int qloc = wm * 16 + (lane >> 2);
    const float inv0 = 1.0f / (l_sm[qloc + 0] + l_sm[64 + qloc + 0]);
    const float inv1 = 1.0f / (l_sm[qloc + 8] + l_sm[64 + qloc + 8]);

    float ctxa[4][4];
#pragma unroll
    for (int f = 0; f < 4; f++)
#pragma unroll
        for (int k = 0; k < 4; k++) ctxa[f][k] = 0.0f;

    // ================= PASS B: normalized attn + PV =================
    attn_issueKV(sm, 0, Kh_, Kl_, Vth_, Vtl_, bh, 0, tid);

    for (int k0 = 0; k0 <= q0; k0 += 64) {
        const int s = (k0 >> 6) & 1;
        cp_wait0();
        __syncthreads();
        if (k0 + 64 <= q0)
            attn_issueKV(sm, s ^ 1, Kh_, Kl_, Vth_, Vtl_, bh, k0 + 64, tid);

        __nv_bfloat16* Kh = sm + s * 4 * ATILE;
        __nv_bfloat16* Kl = Kh + ATILE;
        __nv_bfloat16* Vh = Kl + ATILE;
        __nv_bfloat16* Vl = Vh + ATILE;

        float sa[4][4];
#pragma unroll
        for (int f = 0; f < 4; f++)
#pragma unroll
            for (int k = 0; k < 4; k++) sa[f][k] = 0.0f;

#pragma unroll
        for (int kk = 0; kk < 4; kk++) {
#pragma unroll
            for (int nt = 0; nt < 2; nt++) {
                uint32_t bhf[4], blf[4];
                const int r = wn * 32 + nt * 16 + (lane & 15);
                const int c = kk * 16 + (lane >> 4) * 8;
                ldm_x4(bhf, smem_u32(&Kh[r * APAD + c]));
                ldm_x4(blf, smem_u32(&Kl[r * APAD + c]));
                mma16816(sa[nt * 2 + 0], qfh[kk], bhf[0], bhf[2]);
                mma16816(sa[nt * 2 + 1], qfh[kk], bhf[1], bhf[3]);
                mma16816(sa[nt * 2 + 0], qfh[kk], blf[0], blf[2]);
                mma16816(sa[nt * 2 + 1], qfh[kk], blf[1], blf[3]);
                mma16816(sa[nt * 2 + 0], qfl[kk], bhf[0], bhf[2]);
                mma16816(sa[nt * 2 + 1], qfl[kk], bhf[1], bhf[3]);
            }
        }

        const bool diag = (k0 == q0);
#pragma unroll
        for (int f = 0; f < 4; f++) {
            const int jc = k0 + wn * 32 + f * 8 + (lane & 3) * 2;
#pragma unroll
            for (int half = 0; half < 2; half++) {
                const int qr = qr0 + half * 8;
                const float iv = half ? inv1 : inv0;
                float p0 = exp2f(sa[f][half * 2 + 0]) * iv;
                float p1 = exp2f(sa[f][half * 2 + 1]) * iv;
                if (diag) {
                    if (jc + 0 > qr) p0 = 0.0f;
                    if (jc + 1 > qr) p1 = 0.0f;
                }
                if (write_attn) {
                    const size_t grow = (size_t)(bh * SS + qr);
                    *(float2*)&attn_out[grow * SS + jc] = make_float2(p0, p1);
                }
                const int ql = wm * 16 + (lane >> 2) + half * 8;
                const int jl = wn * 32 + f * 8 + (lane & 3) * 2;
                __nv_bfloat16 h0, l0, h1, l1;
                split2(p0, h0, l0); split2(p1, h1, l1);
                __nv_bfloat162 th, tl;
                th.x = h0; th.y = h1; tl.x = l0; tl.y = l1;
                *(__nv_bfloat162*)&Ph[ql * APAD + jl] = th;
                *(__nv_bfloat162*)&Pl[ql * APAD + jl] = tl;
            }
        }
        __syncthreads();  // Ph/Pl visible

#pragma unroll
        for (int kk = 0; kk < 4; kk++) {
            uint32_t pf_[4], pl_[4];
            {
                const int r = wm * 16 + (lane & 15);
                const int c = kk * 16 + (lane >> 4) * 8;
                ldm_x4(pf_, smem_u32(&Ph[r * APAD + c]));
                ldm_x4(pl_, smem_u32(&Pl[r * APAD + c]));
            }
#pragma unroll
            for (int nt = 0; nt < 2; nt++) {
                uint32_t vh_[4], vl_[4];
                const int r = wn * 32 + nt * 16 + (lane & 15);
                const int c = kk * 16 + (lane >> 4) * 8;
                ldm_x4(vh_, smem_u32(&Vh[r * APAD + c]));
                ldm_x4(vl_, smem_u32(&Vl[r * APAD + c]));
                mma16816(ctxa[nt * 2 + 0], pf_, vh_[0], vh_[2]);
                mma16816(ctxa[nt * 2 + 1], pf_, vh_[1], vh_[3]);
                mma16816(ctxa[nt * 2 + 0], pf_, vl_[0], vl_[2]);
                mma16816(ctxa[nt * 2 + 1], pf_, vl_[1], vl_[3]);
                mma16816(ctxa[nt * 2 + 0], pl_, vh_[0], vh_[2]);
                mma16816(ctxa[nt * 2 + 1], pl_, vh_[1], vh_[3]);
            }
        }
    }

    // ---- ctx write (concat layout) as bf16 hi/lo (already normalized) ----
#pragma unroll
    for (int f = 0; f < 4; f++) {
        const int dc = wn * 32 + f * 8 + (lane & 3) * 2;
        const size_t r0 = (size_t)(b * SS + q0 + qloc);
        __nv_bfloat16 h0, l0, h1, l1;
        __nv_bfloat162 th, tl;
        split2(ctxa[f][0], h0, l0); split2(ctxa[f][1], h1, l1);
        th.x = h0; th.y = h1; tl.x = l0; tl.y = l1;
        *(__nv_bfloat162*)&ctxh[r0 * DD + h * DK + dc] = th;
        *(__nv_bfloat162*)&ctxl[r0 * DD + h * DK + dc] = tl;
        split2(ctxa[f][2], h0, l0); split2(ctxa[f][3], h1, l1);
        th.x = h0; th.y = h1; tl.x = l0; tl.y = l1;
        *(__nv_bfloat162*)&ctxh[(r0 + 8) * DD + h * DK + dc] = th;
        *(__nv_bfloat162*)&ctxl[(r0 + 8) * DD + h * DK + dc] = tl;
    }

    // ---- zero-fill upper-triangle columns [q0+64, SS) for these 64 rows ----
    if (write_attn) {
        const int kend = q0 + 64;
        const int zw = SS - kend;
        if (zw > 0) {
            const int n4 = zw >> 2;
            const size_t base = (size_t)bh * SS * SS;
            const float4 z = make_float4(0.f, 0.f, 0.f, 0.f);
            for (int i = tid; i < 64 * n4; i += 256) {
                const int r = i / n4;
                const int cc = (i - r * n4) << 2;
                *(float4*)&attn_out[base + (size_t)(q0 + r) * SS + kend + cc] = z;
            }
        }
    }
}

// ---------------------------------------------------------------------------
extern "C" void kernel_launch(void* const* d_in, const int* in_sizes, int n_in,
                              void* d_out, int out_size)
{
    const float* Q  = (const float*)d_in[0];
    const float* K  = (const float*)d_in[1];
    const float* V  = (const float*)d_in[2];
    // d_in[3] = causal mask (fixed) — handled analytically
    const float* WQ = (const float*)d_in[4];
    const float* bQ = (const float*)d_in[5];
    const float* WK = (const float*)d_in[6];
    const float* bK = (const float*)d_in[7];
    const float* WV = (const float*)d_in[8];
    const float* bV = (const float*)d_in[9];
    const float* WO = (const float*)d_in[10];
    const float* bO = (const float*)d_in[11];

    __nv_bfloat16 *inh, *inl, *wh, *wl, *qhh, *qhl, *khh, *khl, *vth, *vtl, *cth, *ctl;
    cudaGetSymbolAddress((void**)&inh, g_in_h);
    cudaGetSymbolAddress((void**)&inl, g_in_l);
    cudaGetSymbolAddress((void**)&wh,  g_w_h);
    cudaGetSymbolAddress((void**)&wl,  g_w_l);
    cudaGetSymbolAddress((void**)&qhh, g_qh_h);
    cudaGetSymbolAddress((void**)&qhl, g_qh_l);
    cudaGetSymbolAddress((void**)&khh, g_kh_h);
    cudaGetSymbolAddress((void**)&khl, g_kh_l);
    cudaGetSymbolAddress((void**)&vth, g_vt_h);
    cudaGetSymbolAddress((void**)&vtl, g_vt_l);
    cudaGetSymbolAddress((void**)&cth, g_ctx_h);
    cudaGetSymbolAddress((void**)&ctl, g_ctx_l);

    float* out  = (float*)d_out;
    float* attn = out + OUT_ELEMS;
    const int write_attn =
        ((long long)out_size >= (long long)OUT_ELEMS + ATT_ELEMS) ? 1 : 0;

    cudaFuncSetAttribute(proj_gemm,
                         cudaFuncAttributeMaxDynamicSharedMemorySize, PROJ_SMEM);
    cudaFuncSetAttribute(attn_mma,
                         cudaFuncAttributeMaxDynamicSharedMemorySize, ATT_SMEM);

    convert_all<<<dim3(4096, 7), 256>>>(Q, K, V, WQ, WK, WV, WO);

    // fused Q/K/V projections: grid z = 0,1,2
    proj_gemm<<<dim3(DD / 128, (BB * SS) / 128, 3), 256, PROJ_SMEM>>>(
        inh, inl, wh, wl, cth, ctl, bQ, bK, bV, bO, nullptr,
        qhh, qhl, khh, khl, vth, vtl, -1);

    attn_mma<<<dim3(SS / 64, HH, BB), 256, ATT_SMEM>>>(
        qhh, qhl, khh, khl, vth, vtl, cth, ctl, attn, write_attn);

    // O projection
    proj_gemm<<<dim3(DD / 128, (BB * SS) / 128, 1), 256, PROJ_SMEM>>>(
        inh, inl, wh, wl, cth, ctl, bQ, bK, bV, bO, out,
        qhh, qhl, khh, khl, vth, vtl, 3);
}

// round 5
// speedup vs baseline: 1.0520x; 1.0520x over previous
#include <cuda_runtime.h>
#include <cuda_bf16.h>
#include <math.h>
#include <stdint.h>

#define BB 2
#define SS 2048
#define DD 1024
#define HH 16
#define DK 64
#define OUT_ELEMS (BB * SS * DD)
#define ATT_ELEMS ((long long)BB * HH * SS * (long long)SS)

// ---------------- scratch (allocation-free rule) ----------------
__device__ __align__(16) __nv_bfloat16 g_in_h[3][4194304];
__device__ __align__(16) __nv_bfloat16 g_in_l[3][4194304];
__device__ __align__(16) __nv_bfloat16 g_w_h[4][1048576];
__device__ __align__(16) __nv_bfloat16 g_w_l[4][1048576];
__device__ __align__(16) __nv_bfloat16 g_qh_h[4194304], g_qh_l[4194304];
__device__ __align__(16) __nv_bfloat16 g_kh_h[4194304], g_kh_l[4194304];
__device__ __align__(16) __nv_bfloat16 g_vt_h[4194304], g_vt_l[4194304];
__device__ __align__(16) __nv_bfloat16 g_ctx_h[4194304], g_ctx_l[4194304];

// ---------------- PTX helpers ----------------
__device__ __forceinline__ uint32_t smem_u32(const void* p) {
    return (uint32_t)__cvta_generic_to_shared(p);
}
__device__ __forceinline__ void ldm_x4(uint32_t* r, uint32_t addr) {
    asm volatile("ldmatrix.sync.aligned.m8n8.x4.shared.b16 {%0,%1,%2,%3}, [%4];\n"
                 : "=r"(r[0]), "=r"(r[1]), "=r"(r[2]), "=r"(r[3]) : "r"(addr));
}
__device__ __forceinline__ void mma16816(float* d, const uint32_t* a,
                                         uint32_t b0, uint32_t b1) {
    asm volatile(
        "mma.sync.aligned.m16n8k16.row.col.f32.bf16.bf16.f32 "
        "{%0,%1,%2,%3}, {%4,%5,%6,%7}, {%8,%9}, {%0,%1,%2,%3};\n"
        : "+f"(d[0]), "+f"(d[1]), "+f"(d[2]), "+f"(d[3])
        : "r"(a[0]), "r"(a[1]), "r"(a[2]), "r"(a[3]), "r"(b0), "r"(b1));
}
__device__ __forceinline__ void split2(float x, __nv_bfloat16& h, __nv_bfloat16& l) {
    h = __float2bfloat16(x);
    l = __float2bfloat16(x - __bfloat162float(h));
}
__device__ __forceinline__ void cp16(uint32_t dst, const void* src) {
    asm volatile("cp.async.cg.shared.global [%0], [%1], 16;\n" :: "r"(dst), "l"(src));
}
__device__ __forceinline__ void cp_commit() { asm volatile("cp.async.commit_group;\n"); }
__device__ __forceinline__ void cp_wait0() { asm volatile("cp.async.wait_group 0;\n" ::: "memory"); }

// ---------------------------------------------------------------------------
// Convert fp32 sources to bf16 hi/lo. grid = (4096, 7).
// ---------------------------------------------------------------------------
__global__ __launch_bounds__(256) void convert_all(
    const float* __restrict__ Q, const float* __restrict__ K,
    const float* __restrict__ V, const float* __restrict__ WQ,
    const float* __restrict__ WK, const float* __restrict__ WV,
    const float* __restrict__ WO)
{
    const int seg = blockIdx.y;
    const int nf4 = (seg < 3) ? (4194304 / 4) : (1048576 / 4);
    const int i = blockIdx.x * 256 + threadIdx.x;
    if (i >= nf4) return;
    const float* src;
    __nv_bfloat16 *dh, *dl;
    switch (seg) {
        case 0: src = Q;  dh = g_in_h[0]; dl = g_in_l[0]; break;
        case 1: src = K;  dh = g_in_h[1]; dl = g_in_l[1]; break;
        case 2: src = V;  dh = g_in_h[2]; dl = g_in_l[2]; break;
        case 3: src = WQ; dh = g_w_h[0];  dl = g_w_l[0];  break;
        case 4: src = WK; dh = g_w_h[1];  dl = g_w_l[1];  break;
        case 5: src = WV; dh = g_w_h[2];  dl = g_w_l[2];  break;
        default: src = WO; dh = g_w_h[3]; dl = g_w_l[3];  break;
    }
    float4 v = ((const float4*)src)[i];
    __nv_bfloat16 h0, l0, h1, l1, h2, l2, h3, l3;
    split2(v.x, h0, l0); split2(v.y, h1, l1);
    split2(v.z, h2, l2); split2(v.w, h3, l3);
    __nv_bfloat162 a, b;
    a.x = h0; a.y = h1; b.x = h2; b.y = h3;
    ((__nv_bfloat162*)dh)[i * 2 + 0] = a;
    ((__nv_bfloat162*)dh)[i * 2 + 1] = b;
    a.x = l0; a.y = l1; b.x = l2; b.y = l3;
    ((__nv_bfloat162*)dl)[i * 2 + 0] = a;
    ((__nv_bfloat162*)dl)[i * 2 + 1] = b;
}

// ---------------------------------------------------------------------------
// Projection GEMM (round-3 proven shape): BK=32, 2-stage cp.async, 128x128
// tile, 8 warps (4m x 2n). Fused z-dispatch: z=0 Q, 1 K, 2 V, which=3: O.
// ---------------------------------------------------------------------------
#define PPAD 40
#define PTILE (128 * PPAD)
#define PSTAGE (4 * PTILE)
#define PROJ_SMEM (2 * PSTAGE * (int)sizeof(__nv_bfloat16))  // 81920

__device__ __forceinline__ void proj_issue(
    __nv_bfloat16* ps, int stage,
    const __nv_bfloat16* Ah_, const __nv_bfloat16* Al_,
    const __nv_bfloat16* Bh_, const __nv_bfloat16* Bl_,
    int bm, int bn, int kt, int tid)
{
    __nv_bfloat16* base = ps + stage * PSTAGE;
#pragma unroll
    for (int t = 0; t < 8; t++) {
        const int idx = tid + t * 256;
        const int arr = idx >> 9, row = (idx >> 2) & 127, ch = idx & 3;
        const __nv_bfloat16* g;
        if (arr == 0)      g = Ah_ + (size_t)(bm * 128 + row) * 1024 + kt + ch * 8;
        else if (arr == 1) g = Al_ + (size_t)(bm * 128 + row) * 1024 + kt + ch * 8;
        else if (arr == 2) g = Bh_ + (size_t)(bn * 128 + row) * 1024 + kt + ch * 8;
        else               g = Bl_ + (size_t)(bn * 128 + row) * 1024 + kt + ch * 8;
        cp16(smem_u32(base + arr * PTILE + row * PPAD + ch * 8), g);
    }
    cp_commit();
}

__global__ __launch_bounds__(256, 2) void proj_gemm(
    const __nv_bfloat16* __restrict__ inh, const __nv_bfloat16* __restrict__ inl,
    const __nv_bfloat16* __restrict__ wh, const __nv_bfloat16* __restrict__ wl,
    const __nv_bfloat16* __restrict__ cth, const __nv_bfloat16* __restrict__ ctl,
    const float* __restrict__ bQ, const float* __restrict__ bK,
    const float* __restrict__ bV, const float* __restrict__ bO,
    float* __restrict__ outO,
    __nv_bfloat16* __restrict__ qhh, __nv_bfloat16* __restrict__ qhl,
    __nv_bfloat16* __restrict__ khh, __nv_bfloat16* __restrict__ khl,
    __nv_bfloat16* __restrict__ vth, __nv_bfloat16* __restrict__ vtl,
    int which)
{
    extern __shared__ __nv_bfloat16 ps[];
    const int tid = threadIdx.x, lane = tid & 31, wid = tid >> 5;
    const int wm = wid >> 1, wn = wid & 1;
    const int bm = blockIdx.y, bn = blockIdx.x;
    const int z = (which >= 0) ? which : (int)blockIdx.z;

    const __nv_bfloat16 *Ah_, *Al_, *Bh_, *Bl_;
    const float* bias;
    __nv_bfloat16 *oh = nullptr, *ol = nullptr;
    int mode; float scale = 1.0f;
    if (z == 0) { Ah_ = inh; Al_ = inl; Bh_ = wh; Bl_ = wl; bias = bQ;
                  oh = qhh; ol = qhl; mode = 1;
                  scale = 0.125f * 1.4426950408889634f; }
    else if (z == 1) { Ah_ = inh + 4194304; Al_ = inl + 4194304;
                       Bh_ = wh + 1048576; Bl_ = wl + 1048576; bias = bK;
                       oh = khh; ol = khl; mode = 1; }
    else if (z == 2) { Ah_ = inh + 2 * 4194304; Al_ = inl + 2 * 4194304;
                       Bh_ = wh + 2 * 1048576; Bl_ = wl + 2 * 1048576; bias = bV;
                       oh = vth; ol = vtl; mode = 2; }
    else { Ah_ = cth; Al_ = ctl; Bh_ = wh + 3 * 1048576; Bl_ = wl + 3 * 1048576;
           bias = bO; mode = 0; }

    float acc[2][8][4];
#pragma unroll
    for (int m = 0; m < 2; m++)
#pragma unroll
        for (int n = 0; n < 8; n++)
#pragma unroll
            for (int k = 0; k < 4; k++) acc[m][n][k] = 0.0f;

    proj_issue(ps, 0, Ah_, Al_, Bh_, Bl_, bm, bn, 0, tid);

    for (int kt = 0; kt < 1024; kt += 32) {
        const int s = (kt >> 5) & 1;
        cp_wait0();
        __syncthreads();
        if (kt + 32 < 1024)
            proj_issue(ps, s ^ 1, Ah_, Al_, Bh_, Bl_, bm, bn, kt + 32, tid);

        __nv_bfloat16* Ah = ps + s * PSTAGE;
        __nv_bfloat16* Al = Ah + PTILE;
        __nv_bfloat16* Bh = Al + PTILE;
        __nv_bfloat16* Bl = Bh + PTILE;

#pragma unroll
        for (int kk = 0; kk < 32; kk += 16) {
            uint32_t ah[2][4], al[2][4];
#pragma unroll
            for (int mt = 0; mt < 2; mt++) {
                const int r = wm * 32 + mt * 16 + (lane & 15);
                const int c = kk + (lane >> 4) * 8;
                ldm_x4(ah[mt], smem_u32(&Ah[r * PPAD + c]));
                ldm_x4(al[mt], smem_u32(&Al[r * PPAD + c]));
            }
#pragma unroll
            for (int nt = 0; nt < 4; nt++) {
                uint32_t bh[4], bl[4];
                const int r = wn * 64 + nt * 16 + (lane & 15);
                const int c = kk + (lane >> 4) * 8;
                ldm_x4(bh, smem_u32(&Bh[r * PPAD + c]));
                ldm_x4(bl, smem_u32(&Bl[r * PPAD + c]));
#pragma unroll
                for (int mt = 0; mt < 2; mt++) {
                    mma16816(acc[mt][nt * 2 + 0], ah[mt], bh[0], bh[2]);
                    mma16816(acc[mt][nt * 2 + 1], ah[mt], bh[1], bh[3]);
                    mma16816(acc[mt][nt * 2 + 0], ah[mt], bl[0], bl[2]);
                    mma16816(acc[mt][nt * 2 + 1], ah[mt], bl[1], bl[3]);
                    mma16816(acc[mt][nt * 2 + 0], al[mt], bh[0], bh[2]);
                    mma16816(acc[mt][nt * 2 + 1], al[mt], bh[1], bh[3]);
                }
            }
        }
    }

#pragma unroll
    for (int mt = 0; mt < 2; mt++) {
#pragma unroll
        for (int n8 = 0; n8 < 8; n8++) {
            const int r0 = bm * 128 + wm * 32 + mt * 16 + (lane >> 2);
            const int c  = bn * 128 + wn * 64 + n8 * 8 + (lane & 3) * 2;
            const float b0 = bias[c], b1 = bias[c + 1];
#pragma unroll
            for (int half = 0; half < 2; half++) {
                const int r = r0 + half * 8;
                const float v0 = (acc[mt][n8][half * 2 + 0] + b0) * scale;
                const float v1 = (acc[mt][n8][half * 2 + 1] + b1) * scale;
                if (mode == 0) {
                    *(float2*)&outO[(size_t)r * DD + c] = make_float2(v0, v1);
                } else {
                    const int bb = r >> 11, sidx = r & 2047;
                    const int hh = c >> 6, dk = c & 63;
                    __nv_bfloat16 h0, l0, h1, l1;
                    split2(v0, h0, l0); split2(v1, h1, l1);
                    if (mode == 1) {
                        const size_t a = ((size_t)(bb * HH + hh) * SS + sidx) * DK + dk;
                        __nv_bfloat162 th, tl;
                        th.x = h0; th.y = h1; tl.x = l0; tl.y = l1;
                        *(__nv_bfloat162*)&oh[a] = th;
                        *(__nv_bfloat162*)&ol[a] = tl;
                    } else {
                        const size_t a = ((size_t)(bb * HH + hh) * DK + dk) * SS + sidx;
                        oh[a] = h0; ol[a] = l0;
                        oh[a + SS] = h1; ol[a + SS] = l1;
                    }
                }
            }
        }
    }
}

// ---------------------------------------------------------------------------
// Attention, q-tile 128 (8 warps stacked in q, each warp 16 q rows x 64 cols).
// Two-pass: pass A = row sums (2-term split, K only); pass B = 3-term S,
// normalized attn write, PV. k-tile 64, 2-stage cp.async.
// ---------------------------------------------------------------------------
#define QT 128
#define APAD 72
#define ATILE (64 * APAD)
#define ATT_SMEM (12 * ATILE * (int)sizeof(__nv_bfloat16) + 256)  // 110848

__device__ __forceinline__ void attn_issueKV(
    __nv_bfloat16* sm, int stage,
    const __nv_bfloat16* Kh_, const __nv_bfloat16* Kl_,
    const __nv_bfloat16* Vth_, const __nv_bfloat16* Vtl_,
    int bh, int k0, int tid)
{
    __nv_bfloat16* base = sm + stage * 4 * ATILE;
#pragma unroll
    for (int t = 0; t < 8; t++) {
        const int idx = tid + t * 256;
        const int arr = idx >> 9, row = (idx >> 3) & 63, ch = idx & 7;
        const __nv_bfloat16* g;
        if (arr == 0)      g = Kh_ + ((size_t)bh * SS + k0 + row) * DK + ch * 8;
        else if (arr == 1) g = Kl_ + ((size_t)bh * SS + k0 + row) * DK + ch * 8;
        else if (arr == 2) g = Vth_ + ((size_t)bh * DK + row) * SS + k0 + ch * 8;
        else               g = Vtl_ + ((size_t)bh * DK + row) * SS + k0 + ch * 8;
        cp16(smem_u32(base + arr * ATILE + row * APAD + ch * 8), g);
    }
    cp_commit();
}

__device__ __forceinline__ void attn_issueK(
    __nv_bfloat16* sm, int stage,
    const __nv_bfloat16* Kh_, const __nv_bfloat16* Kl_,
    int bh, int k0, int tid)
{
    __nv_bfloat16* base = sm + stage * 4 * ATILE;
#pragma unroll
    for (int t = 0; t < 4; t++) {
        const int idx = tid + t * 256;
        const int arr = idx >> 9, row = (idx >> 3) & 63, ch = idx & 7;
        const __nv_bfloat16* g = (arr ? Kl_ : Kh_) +
            ((size_t)bh * SS + k0 + row) * DK + ch * 8;
        cp16(smem_u32(base + arr * ATILE + row * APAD + ch * 8), g);
    }
    cp_commit();
}

__global__ __launch_bounds__(256, 2) void attn_mma(
    const __nv_bfloat16* __restrict__ Qh_, const __nv_bfloat16* __restrict__ Ql_,
    const __nv_bfloat16* __restrict__ Kh_, const __nv_bfloat16* __restrict__ Kl_,
    const __nv_bfloat16* __restrict__ Vth_, const __nv_bfloat16* __restrict__ Vtl_,
    __nv_bfloat16* __restrict__ ctxh, __nv_bfloat16* __restrict__ ctxl,
    float* __restrict__ attn_out, int write_attn)
{
    extern __shared__ __nv_bfloat16 sm[];
    __nv_bfloat16* Ph = sm + 8 * ATILE;   // 128 x APAD
    __nv_bfloat16* Pl = sm + 10 * ATILE;  // 128 x APAD

    const int tid = threadIdx.x, lane = tid & 31, wid = tid >> 5;
    const int b = blockIdx.z, h = blockIdx.y, bh = b * HH + h;
    const int q0 = ((int)gridDim.x - 1 - (int)blockIdx.x) * QT;  // longest first

    // ---- prologue: Q tile (128 rows) -> Ph/Pl, K tile 0 -> stage 0 ----
#pragma unroll
    for (int t = 0; t < 8; t++) {
        const int idx = tid + t * 256;
        const int arr = idx >> 10, row = (idx >> 3) & 127, ch = idx & 7;
        const __nv_bfloat16* g =
            (arr ? Ql_ : Qh_) + ((size_t)bh * SS + q0 + row) * DK + ch * 8;
        cp16(smem_u32((arr ? Pl : Ph) + row * APAD + ch * 8), g);
    }
    cp_commit();
    attn_issueK(sm, 0, Kh_, Kl_, bh, 0, tid);
    cp_wait0();
    __syncthreads();

    uint32_t qfh[4][4], qfl[4][4];
#pragma unroll
    for (int kk = 0; kk < 4; kk++) {
        const int r = wid * 16 + (lane & 15);
        const int c = kk * 16 + (lane >> 4) * 8;
        ldm_x4(qfh[kk], smem_u32(&Ph[r * APAD + c]));
        ldm_x4(qfl[kk], smem_u32(&Pl[r * APAD + c]));
    }
    __syncthreads();  // all warps done reading Q staging before P overwrites

    const int qr0 = q0 + wid * 16 + (lane >> 2);
    const int kend = q0 + 64;  // last k-tile start
    float lacc0 = 0.0f, lacc1 = 0.0f;

    // ================= PASS A: row sums (2-term) =================
    for (int k0 = 0; k0 <= kend; k0 += 64) {
        const int s = (k0 >> 6) & 1;
        cp_wait0();
        __syncthreads();
        if (k0 + 64 <= kend)
            attn_issueK(sm, s ^ 1, Kh_, Kl_, bh, k0 + 64, tid);

        __nv_bfloat16* Kh = sm + s * 4 * ATILE;
        __nv_bfloat16* Kl = Kh + ATILE;

        float sa[8][4];
#pragma unroll
        for (int f = 0; f < 8; f++)
#pragma unroll
            for (int k = 0; k < 4; k++) sa[f][k] = 0.0f;

#pragma unroll
        for (int kk = 0; kk < 4; kk++) {
#pragma unroll
            for (int nt = 0; nt < 4; nt++) {
                uint32_t bhf[4], blf[4];
                const int r = nt * 16 + (lane & 15);
                const int c = kk * 16 + (lane >> 4) * 8;
                ldm_x4(bhf, smem_u32(&Kh[r * APAD + c]));
                ldm_x4(blf, smem_u32(&Kl[r * APAD + c]));
                mma16816(sa[nt * 2 + 0], qfh[kk], bhf[0], bhf[2]);
                mma16816(sa[nt * 2 + 1], qfh[kk], bhf[1], bhf[3]);
                mma16816(sa[nt * 2 + 0], qfh[kk], blf[0], blf[2]);
                mma16816(sa[nt * 2 + 1], qfh[kk], blf[1], blf[3]);
            }
        }

        const bool diag = (k0 + 63 > q0 + wid * 16);
#pragma unroll
        for (int f = 0; f < 8; f++) {
            const int jc = k0 + (f >> 1) * 16 + (f & 1) * 8 + (lane & 3) * 2;
#pragma unroll
            for (int half = 0; half < 2; half++) {
                const int qr = qr0 + half * 8;
                float p0 = exp2f(sa[f][half * 2 + 0]);
                float p1 = exp2f(sa[f][half * 2 + 1]);
                if (diag) {
                    if (jc + 0 > qr) p0 = 0.0f;
                    if (jc + 1 > qr) p1 = 0.0f;
                }
                if (half == 0) lacc0 += p0 + p1; else lacc1 += p0 + p1;
            }
        }
    }

    lacc0 += __shfl_xor_sync(0xffffffffu, lacc0, 1);
    lacc0 += __shfl_xor_sync(0xffffffffu, lacc0, 2);
    lacc1 += __shfl_xor_sync(0xffffffffu, lacc1, 1);
    lacc1 += __shfl_xor_sync(0xffffffffu, lacc1, 2);
    const float inv0 = 1.0f / lacc0;
    const float inv1 = 1.0f / lacc1;

    float ctxa[8][4];
#pragma unroll
    for (int f = 0; f < 8; f++)
#pragma unroll
        for (int k = 0; k < 4; k++) ctxa[f][k] = 0.0f;

    // ================= PASS B: normalized attn + PV (3-term) =================
    cp_wait0();
    __syncthreads();
    attn_issueKV(sm, 0, Kh_, Kl_, Vth_, Vtl_, bh, 0, tid);

    for (int k0 = 0; k0 <= kend; k0 += 64) {
        const int s = (k0 >> 6) & 1;
        cp_wait0();
        __syncthreads();
        if (k0 + 64 <= kend)
            attn_issueKV(sm, s ^ 1, Kh_, Kl_, Vth_, Vtl_, bh, k0 + 64, tid);

        __nv_bfloat16* Kh = sm + s * 4 * ATILE;
        __nv_bfloat16* Kl = Kh + ATILE;
        __nv_bfloat16* Vh = Kl + ATILE;
        __nv_bfloat16* Vl = Vh + ATILE;

        float sa[8][4];
#pragma unroll
        for (int f = 0; f < 8; f++)
#pragma unroll
            for (int k = 0; k < 4; k++) sa[f][k] = 0.0f;

#pragma unroll
        for (int kk = 0; kk < 4; kk++) {
#pragma unroll
            for (int nt = 0; nt < 4; nt++) {
                uint32_t bhf[4], blf[4];
                const int r = nt * 16 + (lane & 15);
                const int c = kk * 16 + (lane >> 4) * 8;
                ldm_x4(bhf, smem_u32(&Kh[r * APAD + c]));
                ldm_x4(blf, smem_u32(&Kl[r * APAD + c]));
                mma16816(sa[nt * 2 + 0], qfh[kk], bhf[0], bhf[2]);
                mma16816(sa[nt * 2 + 1], qfh[kk], bhf[1], bhf[3]);
                mma16816(sa[nt * 2 + 0], qfh[kk], blf[0], blf[2]);
                mma16816(sa[nt * 2 + 1], qfh[kk], blf[1], blf[3]);
                mma16816(sa[nt * 2 + 0], qfl[kk], bhf[0], bhf[2]);
                mma16816(sa[nt * 2 + 1], qfl[kk], bhf[1], bhf[3]);
            }
        }

        const bool diag = (k0 + 63 > q0 + wid * 16);
#pragma unroll
        for (int f = 0; f < 8; f++) {
            const int jc = k0 + (f >> 1) * 16 + (f & 1) * 8 + (lane & 3) * 2;
#pragma unroll
            for (int half = 0; half < 2; half++) {
                const int qr = qr0 + half * 8;
                const float iv = half ? inv1 : inv0;
                float p0 = exp2f(sa[f][half * 2 + 0]) * iv;
                float p1 = exp2f(sa[f][half * 2 + 1]) * iv;
                if (diag) {
                    if (jc + 0 > qr) p0 = 0.0f;
                    if (jc + 1 > qr) p1 = 0.0f;
                }
                if (write_attn) {
                    const size_t grow = (size_t)(bh * SS + qr);
                    *(float2*)&attn_out[grow * SS + jc] = make_float2(p0, p1);
                }
                const int ql = wid * 16 + (lane >> 2) + half * 8;
                const int jl = (f >> 1) * 16 + (f & 1) * 8 + (lane & 3) * 2;
                __nv_bfloat16 h0, l0, h1, l1;
                split2(p0, h0, l0); split2(p1, h1, l1);
                __nv_bfloat162 th, tl;
                th.x = h0; th.y = h1; tl.x = l0; tl.y = l1;
                *(__nv_bfloat162*)&Ph[ql * APAD + jl] = th;
                *(__nv_bfloat162*)&Pl[ql * APAD + jl] = tl;
            }
        }
        __syncthreads();  // Ph/Pl visible

#pragma unroll
        for (int kk = 0; kk < 4; kk++) {
            uint32_t pf_[4], pl_[4];
            {
                const int r = wid * 16 + (lane & 15);
                const int c = kk * 16 + (lane >> 4) * 8;
                ldm_x4(pf_, smem_u32(&Ph[r * APAD + c]));
                ldm_x4(pl_, smem_u32(&Pl[r * APAD + c]));
            }
#pragma unroll
            for (int nt = 0; nt < 4; nt++) {
                uint32_t vh_[4], vl_[4];
                const int r = nt * 16 + (lane & 15);
                const int c = kk * 16 + (lane >> 4) * 8;
                ldm_x4(vh_, smem_u32(&Vh[r * APAD + c]));
                ldm_x4(vl_, smem_u32(&Vl[r * APAD + c]));
                mma16816(ctxa[nt * 2 + 0], pf_, vh_[0], vh_[2]);
                mma16816(ctxa[nt * 2 + 1], pf_, vh_[1], vh_[3]);
                mma16816(ctxa[nt * 2 + 0], pf_, vl_[0], vl_[2]);
                mma16816(ctxa[nt * 2 + 1], pf_, vl_[1], vl_[3]);
                mma16816(ctxa[nt * 2 + 0], pl_, vh_[0], vh_[2]);
                mma16816(ctxa[nt * 2 + 1], pl_, vh_[1], vh_[3]);
            }
        }
    }

    // ---- ctx write (concat layout) as bf16 hi/lo (already normalized) ----
    const int qloc = wid * 16 + (lane >> 2);
#pragma unroll
    for (int f = 0; f < 8; f++) {
        const int dc = (f >> 1) * 16 + (f & 1) * 8 + (lane & 3) * 2;
        const size_t r0 = (size_t)(b * SS + q0 + qloc);
        __nv_bfloat16 h0, l0, h1, l1;
        __nv_bfloat162 th, tl;
        split2(ctxa[f][0], h0, l0); split2(ctxa[f][1], h1, l1);
        th.x = h0; th.y = h1; tl.x = l0; tl.y = l1;
        *(__nv_bfloat162*)&ctxh[r0 * DD + h * DK + dc] = th;
        *(__nv_bfloat162*)&ctxl[r0 * DD + h * DK + dc] = tl;
        split2(ctxa[f][2], h0, l0); split2(ctxa[f][3], h1, l1);
        th.x = h0; th.y = h1; tl.x = l0; tl.y = l1;
        *(__nv_bfloat162*)&ctxh[(r0 + 8) * DD + h * DK + dc] = th;
        *(__nv_bfloat162*)&ctxl[(r0 + 8) * DD + h * DK + dc] = tl;
    }

    // ---- zero-fill columns [q0+128, SS) for these 128 rows ----
    if (write_attn) {
        const int zstart = q0 + QT;
        const int zw = SS - zstart;
        if (zw > 0) {
            const int n4 = zw >> 2;
            const size_t base = (size_t)bh * SS * SS;
            const float4 z = make_float4(0.f, 0.f, 0.f, 0.f);
            for (int i = tid; i < QT * n4; i += 256) {
                const int r = i / n4;
                const int cc = (i - r * n4) << 2;
                *(float4*)&attn_out[base + (size_t)(q0 + r) * SS + zstart + cc] = z;
            }
        }
    }
}

// ---------------------------------------------------------------------------
extern "C" void kernel_launch(void* const* d_in, const int* in_sizes, int n_in,
                              void* d_out, int out_size)
{
    const float* Q  = (const float*)d_in[0];
    const float* K  = (const float*)d_in[1];
    const float* V  = (const float*)d_in[2];
    // d_in[3] = causal mask (fixed) — handled analytically
    const float* WQ = (const float*)d_in[4];
    const float* bQ = (const float*)d_in[5];
    const float* WK = (const float*)d_in[6];
    const float* bK = (const float*)d_in[7];
    const float* WV = (const float*)d_in[8];
    const float* bV = (const float*)d_in[9];
    const float* WO = (const float*)d_in[10];
    const float* bO = (const float*)d_in[11];

    __nv_bfloat16 *inh, *inl, *wh, *wl, *qhh, *qhl, *khh, *khl, *vth, *vtl, *cth, *ctl;
    cudaGetSymbolAddress((void**)&inh, g_in_h);
    cudaGetSymbolAddress((void**)&inl, g_in_l);
    cudaGetSymbolAddress((void**)&wh,  g_w_h);
    cudaGetSymbolAddress((void**)&wl,  g_w_l);
    cudaGetSymbolAddress((void**)&qhh, g_qh_h);
    cudaGetSymbolAddress((void**)&qhl, g_qh_l);
    cudaGetSymbolAddress((void**)&khh, g_kh_h);
    cudaGetSymbolAddress((void**)&khl, g_kh_l);
    cudaGetSymbolAddress((void**)&vth, g_vt_h);
    cudaGetSymbolAddress((void**)&vtl, g_vt_l);
    cudaGetSymbolAddress((void**)&cth, g_ctx_h);
    cudaGetSymbolAddress((void**)&ctl, g_ctx_l);

    float* out  = (float*)d_out;
    float* attn = out + OUT_ELEMS;
    const int write_attn =
        ((long long)out_size >= (long long)OUT_ELEMS + ATT_ELEMS) ? 1 : 0;

    cudaFuncSetAttribute(proj_gemm,
                         cudaFuncAttributeMaxDynamicSharedMemorySize, PROJ_SMEM);
    cudaFuncSetAttribute(attn_mma,
                         cudaFuncAttributeMaxDynamicSharedMemorySize, ATT_SMEM);

    convert_all<<<dim3(4096, 7), 256>>>(Q, K, V, WQ, WK, WV, WO);

    proj_gemm<<<dim3(DD / 128, (BB * SS) / 128, 3), 256, PROJ_SMEM>>>(
        inh, inl, wh, wl, cth, ctl, bQ, bK, bV, bO, nullptr,
        qhh, qhl, khh, khl, vth, vtl, -1);

    attn_mma<<<dim3(SS / QT, HH, BB), 256, ATT_SMEM>>>(
        qhh, qhl, khh, khl, vth, vtl, cth, ctl, attn, write_attn);

    proj_gemm<<<dim3(DD / 128, (BB * SS) / 128, 1), 256, PROJ_SMEM>>>(
        inh, inl, wh, wl, cth, ctl, bQ, bK, bV, bO, out,
        qhh, qhl, khh, khl, vth, vtl, 3);
}

// round 9
// speedup vs baseline: 1.3607x; 1.2934x over previous
#include <cuda_runtime.h>
#include <cuda_fp16.h>
#include <math.h>
#include <stdint.h>

#define BB 2
#define SS 2048
#define DD 1024
#define HH 16
#define DK 64
#define OUT_ELEMS (BB * SS * DD)
#define ATT_ELEMS ((long long)BB * HH * SS * (long long)SS)

// ---------------- scratch (allocation-free rule) ----------------
// A-side operands: plain fp16. B-side operands: fp16 hi/lo pairs.
__device__ __align__(16) __half g_in[3][4194304];              // Q,K,V inputs (A)
__device__ __align__(16) __half g_w_h[4][1048576], g_w_l[4][1048576];  // weights (B)
__device__ __align__(16) __half g_qh[4194304];                 // Q heads (A of QK)
__device__ __align__(16) __half g_kh_h[4194304], g_kh_l[4194304];  // K heads (B of QK)
__device__ __align__(16) __half g_vt_h[4194304], g_vt_l[4194304];  // V^T (B of PV)
__device__ __align__(16) __half g_ctx[4194304];                // ctx (A of O-proj)

// ---------------- PTX helpers ----------------
__device__ __forceinline__ uint32_t smem_u32(const void* p) {
    return (uint32_t)__cvta_generic_to_shared(p);
}
__device__ __forceinline__ void ldm_x4(uint32_t* r, uint32_t addr) {
    asm volatile("ldmatrix.sync.aligned.m8n8.x4.shared.b16 {%0,%1,%2,%3}, [%4];\n"
                 : "=r"(r[0]), "=r"(r[1]), "=r"(r[2]), "=r"(r[3]) : "r"(addr));
}
__device__ __forceinline__ void mma16816(float* d, const uint32_t* a,
                                         uint32_t b0, uint32_t b1) {
    asm volatile(
        "mma.sync.aligned.m16n8k16.row.col.f32.f16.f16.f32 "
        "{%0,%1,%2,%3}, {%4,%5,%6,%7}, {%8,%9}, {%0,%1,%2,%3};\n"
        : "+f"(d[0]), "+f"(d[1]), "+f"(d[2]), "+f"(d[3])
        : "r"(a[0]), "r"(a[1]), "r"(a[2]), "r"(a[3]), "r"(b0), "r"(b1));
}
__device__ __forceinline__ void split2h(float x, __half& h, __half& l) {
    h = __float2half(x);
    l = __float2half(x - __half2float(h));
}
__device__ __forceinline__ void cp16(uint32_t dst, const void* src) {
    asm volatile("cp.async.cg.shared.global [%0], [%1], 16;\n" :: "r"(dst), "l"(src));
}
__device__ __forceinline__ void cp_commit() { asm volatile("cp.async.commit_group;\n"); }
__device__ __forceinline__ void cp_wait0() { asm volatile("cp.async.wait_group 0;\n" ::: "memory"); }

// ---------------------------------------------------------------------------
// Convert fp32 sources. Inputs (A-side): fp16 plain. Weights (B-side): hi/lo.
// grid = (4096, 7).
// ---------------------------------------------------------------------------
__global__ __launch_bounds__(256) void convert_all(
    const float* __restrict__ Q, const float* __restrict__ K,
    const float* __restrict__ V, const float* __restrict__ WQ,
    const float* __restrict__ WK, const float* __restrict__ WV,
    const float* __restrict__ WO)
{
    const int seg = blockIdx.y;
    const int nf4 = (seg < 3) ? (4194304 / 4) : (1048576 / 4);
    const int i = blockIdx.x * 256 + threadIdx.x;
    if (i >= nf4) return;
    if (seg < 3) {
        const float* src = (seg == 0) ? Q : (seg == 1) ? K : V;
        __half* dh = g_in[seg];
        float4 v = ((const float4*)src)[i];
        ((__half2*)dh)[i * 2 + 0] = __floats2half2_rn(v.x, v.y);
        ((__half2*)dh)[i * 2 + 1] = __floats2half2_rn(v.z, v.w);
    } else {
        const int w = seg - 3;
        const float* src = (w == 0) ? WQ : (w == 1) ? WK : (w == 2) ? WV : WO;
        __half *dh = g_w_h[w], *dl = g_w_l[w];
        float4 v = ((const float4*)src)[i];
        __half h0, l0, h1, l1, h2, l2, h3, l3;
        split2h(v.x, h0, l0); split2h(v.y, h1, l1);
        split2h(v.z, h2, l2); split2h(v.w, h3, l3);
        ((__half2*)dh)[i * 2 + 0] = __halves2half2(h0, h1);
        ((__half2*)dh)[i * 2 + 1] = __halves2half2(h2, h3);
        ((__half2*)dl)[i * 2 + 0] = __halves2half2(l0, l1);
        ((__half2*)dl)[i * 2 + 1] = __halves2half2(l2, l3);
    }
}

// ---------------------------------------------------------------------------
// Projection GEMM: out = A @ B^T + bias. A plain fp16, B hi/lo fp16.
// BK=32, 2-stage cp.async, 128x128 tile, 8 warps (4m x 2n), 2 MMAs/fragment.
// z: 0=Q (scaled, hi-only out), 1=K (hi/lo out), 2=V (V^T hi/lo), 3=O (fp32).
// ---------------------------------------------------------------------------
#define PPAD 40
#define PTILE (128 * PPAD)
#define PSTAGE (3 * PTILE)
#define PROJ_SMEM (2 * PSTAGE * (int)sizeof(__half))  // 61440

__device__ __forceinline__ void proj_issue(
    __half* ps, int stage,
    const __half* A_, const __half* Bh_, const __half* Bl_,
    int bm, int bn, int kt, int tid)
{
    __half* base = ps + stage * PSTAGE;
#pragma unroll
    for (int t = 0; t < 6; t++) {
        const int idx = tid + t * 256;
        const int arr = idx >> 9, row = (idx >> 2) & 127, ch = idx & 3;
        const __half* g;
        if (arr == 0)      g = A_  + (size_t)(bm * 128 + row) * 1024 + kt + ch * 8;
        else if (arr == 1) g = Bh_ + (size_t)(bn * 128 + row) * 1024 + kt + ch * 8;
        else               g = Bl_ + (size_t)(bn * 128 + row) * 1024 + kt + ch * 8;
        cp16(smem_u32(base + arr * PTILE + row * PPAD + ch * 8), g);
    }
    cp_commit();
}

__global__ __launch_bounds__(256, 2) void proj_gemm(
    const __half* __restrict__ in0, const __half* __restrict__ in1,
    const __half* __restrict__ in2, const __half* __restrict__ ctx,
    const __half* __restrict__ wh, const __half* __restrict__ wl,
    const float* __restrict__ bQ, const float* __restrict__ bK,
    const float* __restrict__ bV, const float* __restrict__ bO,
    float* __restrict__ outO,
    __half* __restrict__ qh, __half* __restrict__ khh, __half* __restrict__ khl,
    __half* __restrict__ vth, __half* __restrict__ vtl,
    int which)
{
    extern __shared__ __half ps[];
    const int tid = threadIdx.x, lane = tid & 31, wid = tid >> 5;
    const int wm = wid >> 1, wn = wid & 1;
    const int bm = blockIdx.y, bn = blockIdx.x;
    const int z = (which >= 0) ? which : (int)blockIdx.z;

    const __half *A_, *Bh_, *Bl_;
    const float* bias;
    int mode; float scale = 1.0f;
    if (z == 0)      { A_ = in0; Bh_ = wh; Bl_ = wl; bias = bQ; mode = 1;
                       scale = 0.125f * 1.4426950408889634f; }
    else if (z == 1) { A_ = in1; Bh_ = wh + 1048576; Bl_ = wl + 1048576;
                       bias = bK; mode = 2; }
    else if (z == 2) { A_ = in2; Bh_ = wh + 2 * 1048576; Bl_ = wl + 2 * 1048576;
                       bias = bV; mode = 3; }
    else             { A_ = ctx; Bh_ = wh + 3 * 1048576; Bl_ = wl + 3 * 1048576;
                       bias = bO; mode = 0; }

    float acc[2][8][4];
#pragma unroll
    for (int m = 0; m < 2; m++)
#pragma unroll
        for (int n = 0; n < 8; n++)
#pragma unroll
            for (int k = 0; k < 4; k++) acc[m][n][k] = 0.0f;

    proj_issue(ps, 0, A_, Bh_, Bl_, bm, bn, 0, tid);

    for (int kt = 0; kt < 1024; kt += 32) {
        const int s = (kt >> 5) & 1;
        cp_wait0();
        __syncthreads();
        if (kt + 32 < 1024)
            proj_issue(ps, s ^ 1, A_, Bh_, Bl_, bm, bn, kt + 32, tid);

        __half* Ah = ps + s * PSTAGE;
        __half* Bh = Ah + PTILE;
        __half* Bl = Bh + PTILE;

#pragma unroll
        for (int kk = 0; kk < 32; kk += 16) {
            uint32_t ah[2][4];
#pragma unroll
            for (int mt = 0; mt < 2; mt++) {
                const int r = wm * 32 + mt * 16 + (lane & 15);
                const int c = kk + (lane >> 4) * 8;
                ldm_x4(ah[mt], smem_u32(&Ah[r * PPAD + c]));
            }
#pragma unroll
            for (int nt = 0; nt < 4; nt++) {
                uint32_t bh[4], bl[4];
                const int r = wn * 64 + nt * 16 + (lane & 15);
                const int c = kk + (lane >> 4) * 8;
                ldm_x4(bh, smem_u32(&Bh[r * PPAD + c]));
                ldm_x4(bl, smem_u32(&Bl[r * PPAD + c]));
#pragma unroll
                for (int mt = 0; mt < 2; mt++) {
                    mma16816(acc[mt][nt * 2 + 0], ah[mt], bh[0], bh[2]);
                    mma16816(acc[mt][nt * 2 + 1], ah[mt], bh[1], bh[3]);
                    mma16816(acc[mt][nt * 2 + 0], ah[mt], bl[0], bl[2]);
                    mma16816(acc[mt][nt * 2 + 1], ah[mt], bl[1], bl[3]);
                }
            }
        }
    }

#pragma unroll
    for (int mt = 0; mt < 2; mt++) {
#pragma unroll
        for (int n8 = 0; n8 < 8; n8++) {
            const int r0 = bm * 128 + wm * 32 + mt * 16 + (lane >> 2);
            const int c  = bn * 128 + wn * 64 + n8 * 8 + (lane & 3) * 2;
            const float b0 = bias[c], b1 = bias[c + 1];
#pragma unroll
            for (int half_ = 0; half_ < 2; half_++) {
                const int r = r0 + half_ * 8;
                const float v0 = (acc[mt][n8][half_ * 2 + 0] + b0) * scale;
                const float v1 = (acc[mt][n8][half_ * 2 + 1] + b1) * scale;
                const int bb = r >> 11, sidx = r & 2047;
                const int hh = c >> 6, dk = c & 63;
                if (mode == 0) {
                    *(float2*)&outO[(size_t)r * DD + c] = make_float2(v0, v1);
                } else if (mode == 1) {       // Q heads: hi only
                    const size_t a = ((size_t)(bb * HH + hh) * SS + sidx) * DK + dk;
                    *(__half2*)&qh[a] = __floats2half2_rn(v0, v1);
                } else if (mode == 2) {       // K heads: hi/lo
                    const size_t a = ((size_t)(bb * HH + hh) * SS + sidx) * DK + dk;
                    __half h0, l0, h1, l1;
                    split2h(v0, h0, l0); split2h(v1, h1, l1);
                    *(__half2*)&khh[a] = __halves2half2(h0, h1);
                    *(__half2*)&khl[a] = __halves2half2(l0, l1);
                } else {                      // V^T [bh][dk][s]: hi/lo
                    const size_t a = ((size_t)(bb * HH + hh) * DK + dk) * SS + sidx;
                    __half h0, l0, h1, l1;
                    split2h(v0, h0, l0); split2h(v1, h1, l1);
                    vth[a] = h0; vtl[a] = l0;
                    vth[a + SS] = h1; vtl[a + SS] = l1;
                }
            }
        }
    }
}

// ---------------------------------------------------------------------------
// Attention, q-tile 128 (8 warps stacked in q). Two-pass. Q/P plain fp16 (A),
// K/V hi/lo fp16 (B), 2 MMAs per fragment. k-tile 64, 2-stage cp.async.
// ---------------------------------------------------------------------------
#define QT 128
#define APAD 72
#define ATILE (64 * APAD)
#define ATT_SMEM (10 * ATILE * (int)sizeof(__half) + 256)  // 92416

__device__ __forceinline__ void attn_issueKV(
    __half* sm, int stage,
    const __half* Kh_, const __half* Kl_,
    const __half* Vth_, const __half* Vtl_,
    int bh, int k0, int tid)
{
    __half* base = sm + stage * 4 * ATILE;
#pragma unroll
    for (int t = 0; t < 8; t++) {
        const int idx = tid + t * 256;
        const int arr = idx >> 9, row = (idx >> 3) & 63, ch = idx & 7;
        const __half* g;
        if (arr == 0)      g = Kh_ + ((size_t)bh * SS + k0 + row) * DK + ch * 8;
        else if (arr == 1) g = Kl_ + ((size_t)bh * SS + k0 + row) * DK + ch * 8;
        else if (arr == 2) g = Vth_ + ((size_t)bh * DK + row) * SS + k0 + ch * 8;
        else               g = Vtl_ + ((size_t)bh * DK + row) * SS + k0 + ch * 8;
        cp16(smem_u32(base + arr * ATILE + row * APAD + ch * 8), g);
    }
    cp_commit();
}

__device__ __forceinline__ void attn_issueK(
    __half* sm, int stage,
    const __half* Kh_, const __half* Kl_,
    int bh, int k0, int tid)
{
    __half* base = sm + stage * 4 * ATILE;
#pragma unroll
    for (int t = 0; t < 4; t++) {
        const int idx = tid + t * 256;
        const int arr = idx >> 9, row = (idx >> 3) & 63, ch = idx & 7;
        const __half* g = (arr ? Kl_ : Kh_) +
            ((size_t)bh * SS + k0 + row) * DK + ch * 8;
        cp16(smem_u32(base + arr * ATILE + row * APAD + ch * 8), g);
    }
    cp_commit();
}

__global__ __launch_bounds__(256, 2) void attn_mma(
    const __half* __restrict__ Qh_,
    const __half* __restrict__ Kh_, const __half* __restrict__ Kl_,
    const __half* __restrict__ Vth_, const __half* __restrict__ Vtl_,
    __half* __restrict__ ctx,
    float* __restrict__ attn_out, int write_attn)
{
    extern __shared__ __half sm[];
    __half* Ph = sm + 8 * ATILE;   // 128 x APAD

    const int tid = threadIdx.x, lane = tid & 31, wid = tid >> 5;
    const int b = blockIdx.z, h = blockIdx.y, bh = b * HH + h;
    const int q0 = ((int)gridDim.x - 1 - (int)blockIdx.x) * QT;  // longest first

    // ---- prologue: Q tile (hi only) -> Ph, K tile 0 -> stage 0 ----
#pragma unroll
    for (int t = 0; t < 4; t++) {
        const int idx = tid + t * 256;
        const int row = (idx >> 3) & 127, ch = idx & 7;
        const __half* g = Qh_ + ((size_t)bh * SS + q0 + row) * DK + ch * 8;
        cp16(smem_u32(Ph + row * APAD + ch * 8), g);
    }
    cp_commit();
    attn_issueK(sm, 0, Kh_, Kl_, bh, 0, tid);
    cp_wait0();
    __syncthreads();

    uint32_t qf[4][4];
#pragma unroll
    for (int kk = 0; kk < 4; kk++) {
        const int r = wid * 16 + (lane & 15);
        const int c = kk * 16 + (lane >> 4) * 8;
        ldm_x4(qf[kk], smem_u32(&Ph[r * APAD + c]));
    }
    __syncthreads();  // Q staging read complete before P overwrites

    const int qr0 = q0 + wid * 16 + (lane >> 2);
    const int kend = q0 + 64;
    float lacc0 = 0.0f, lacc1 = 0.0f;

    // ================= PASS A: row sums =================
    for (int k0 = 0; k0 <= kend; k0 += 64) {
        const int s = (k0 >> 6) & 1;
        cp_wait0();
        __syncthreads();
        if (k0 + 64 <= kend)
            attn_issueK(sm, s ^ 1, Kh_, Kl_, bh, k0 + 64, tid);

        __half* Kh = sm + s * 4 * ATILE;
        __half* Kl = Kh + ATILE;

        float sa[8][4];
#pragma unroll
        for (int f = 0; f < 8; f++)
#pragma unroll
            for (int k = 0; k < 4; k++) sa[f][k] = 0.0f;

#pragma unroll
        for (int kk = 0; kk < 4; kk++) {
#pragma unroll
            for (int nt = 0; nt < 4; nt++) {
                uint32_t bhf[4], blf[4];
                const int r = nt * 16 + (lane & 15);
                const int c = kk * 16 + (lane >> 4) * 8;
                ldm_x4(bhf, smem_u32(&Kh[r * APAD + c]));
                ldm_x4(blf, smem_u32(&Kl[r * APAD + c]));
                mma16816(sa[nt * 2 + 0], qf[kk], bhf[0], bhf[2]);
                mma16816(sa[nt * 2 + 1], qf[kk], bhf[1], bhf[3]);
                mma16816(sa[nt * 2 + 0], qf[kk], blf[0], blf[2]);
                mma16816(sa[nt * 2 + 1], qf[kk], blf[1], blf[3]);
            }
        }

        const bool diag = (k0 + 63 > q0 + wid * 16);
#pragma unroll
        for (int f = 0; f < 8; f++) {
            const int jc = k0 + (f >> 1) * 16 + (f & 1) * 8 + (lane & 3) * 2;
#pragma unroll
            for (int half_ = 0; half_ < 2; half_++) {
                const int qr = qr0 + half_ * 8;
                float p0 = exp2f(sa[f][half_ * 2 + 0]);
                float p1 = exp2f(sa[f][half_ * 2 + 1]);
                if (diag) {
                    if (jc + 0 > qr) p0 = 0.0f;
                    if (jc + 1 > qr) p1 = 0.0f;
                }
                if (half_ == 0) lacc0 += p0 + p1; else lacc1 += p0 + p1;
            }
        }
    }

    lacc0 += __shfl_xor_sync(0xffffffffu, lacc0, 1);
    lacc0 += __shfl_xor_sync(0xffffffffu, lacc0, 2);
    lacc1 += __shfl_xor_sync(0xffffffffu, lacc1, 1);
    lacc1 += __shfl_xor_sync(0xffffffffu, lacc1, 2);
    const float inv0 = 1.0f / lacc0;
    const float inv1 = 1.0f / lacc1;

    float ctxa[8][4];
#pragma unroll
    for (int f = 0; f < 8; f++)
#pragma unroll
        for (int k = 0; k < 4; k++) ctxa[f][k] = 0.0f;

    // ================= PASS B: normalized attn + PV =================
    cp_wait0();
    __syncthreads();
    attn_issueKV(sm, 0, Kh_, Kl_, Vth_, Vtl_, bh, 0, tid);

    for (int k0 = 0; k0 <= kend; k0 += 64) {
        const int s = (k0 >> 6) & 1;
        cp_wait0();
        __syncthreads();
        if (k0 + 64 <= kend)
            attn_issueKV(sm, s ^ 1, Kh_, Kl_, Vth_, Vtl_, bh, k0 + 64, tid);

        __half* Kh = sm + s * 4 * ATILE;
        __half* Kl = Kh + ATILE;
        __half* Vh = Kl + ATILE;
        __half* Vl = Vh + ATILE;

        float sa[8][4];
#pragma unroll
        for (int f = 0; f < 8; f++)
#pragma unroll
            for (int k = 0; k < 4; k++) sa[f][k] = 0.0f;

#pragma unroll
        for (int kk = 0; kk < 4; kk++) {
#pragma unroll
            for (int nt = 0; nt < 4; nt++) {
                uint32_t bhf[4], blf[4];
                const int r = nt * 16 + (lane & 15);
                const int c = kk * 16 + (lane >> 4) * 8;
                ldm_x4(bhf, smem_u32(&Kh[r * APAD + c]));
                ldm_x4(blf, smem_u32(&Kl[r * APAD + c]));
                mma16816(sa[nt * 2 + 0], qf[kk], bhf[0], bhf[2]);
                mma16816(sa[nt * 2 + 1], qf[kk], bhf[1], bhf[3]);
                mma16816(sa[nt * 2 + 0], qf[kk], blf[0], blf[2]);
                mma16816(sa[nt * 2 + 1], qf[kk], blf[1], blf[3]);
            }
        }

        const bool diag = (k0 + 63 > q0 + wid * 16);
#pragma unroll
        for (int f = 0; f < 8; f++) {
            const int jc = k0 + (f >> 1) * 16 + (f & 1) * 8 + (lane & 3) * 2;
#pragma unroll
            for (int half_ = 0; half_ < 2; half_++) {
                const int qr = qr0 + half_ * 8;
                const float iv = half_ ? inv1 : inv0;
                float p0 = exp2f(sa[f][half_ * 2 + 0]) * iv;
                float p1 = exp2f(sa[f][half_ * 2 + 1]) * iv;
                if (diag) {
                    if (jc + 0 > qr) p0 = 0.0f;
                    if (jc + 1 > qr) p1 = 0.0f;
                }
                if (write_attn) {
                    const size_t grow = (size_t)(bh * SS + qr);
                    *(float2*)&attn_out[grow * SS + jc] = make_float2(p0, p1);
                }
                const int ql = wid * 16 + (lane >> 2) + half_ * 8;
                const int jl = (f >> 1) * 16 + (f & 1) * 8 + (lane & 3) * 2;
                *(__half2*)&Ph[ql * APAD + jl] = __floats2half2_rn(p0, p1);
            }
        }
        __syncthreads();  // Ph visible

#pragma unroll
        for (int kk = 0; kk < 4; kk++) {
            uint32_t pf_[4];
            {
                const int r = wid * 16 + (lane & 15);
                const int c = kk * 16 + (lane >> 4) * 8;
                ldm_x4(pf_, smem_u32(&Ph[r * APAD + c]));
            }
#pragma unroll
            for (int nt = 0; nt < 4; nt++) {
                uint32_t vh_[4], vl_[4];
                const int r = nt * 16 + (lane & 15);
                const int c = kk * 16 + (lane >> 4) * 8;
                ldm_x4(vh_, smem_u32(&Vh[r * APAD + c]));
                ldm_x4(vl_, smem_u32(&Vl[r * APAD + c]));
                mma16816(ctxa[nt * 2 + 0], pf_, vh_[0], vh_[2]);
                mma16816(ctxa[nt * 2 + 1], pf_, vh_[1], vh_[3]);
                mma16816(ctxa[nt * 2 + 0], pf_, vl_[0], vl_[2]);
                mma16816(ctxa[nt * 2 + 1], pf_, vl_[1], vl_[3]);
            }
        }
    }

    // ---- ctx write (concat layout), plain fp16 ----
    const int qloc = wid * 16 + (lane >> 2);
#pragma unroll
    for (int f = 0; f < 8; f++) {
        const int dc = (f >> 1) * 16 + (f & 1) * 8 + (lane & 3) * 2;
        const size_t r0 = (size_t)(b * SS + q0 + qloc);
        *(__half2*)&ctx[r0 * DD + h * DK + dc] =
            __floats2half2_rn(ctxa[f][0], ctxa[f][1]);
        *(__half2*)&ctx[(r0 + 8) * DD + h * DK + dc] =
            __floats2half2_rn(ctxa[f][2], ctxa[f][3]);
    }

    // ---- zero-fill columns [q0+128, SS) for these 128 rows ----
    if (write_attn) {
        const int zstart = q0 + QT;
        const int zw = SS - zstart;
        if (zw > 0) {
            const int n4 = zw >> 2;
            const size_t base = (size_t)bh * SS * SS;
            const float4 z = make_float4(0.f, 0.f, 0.f, 0.f);
            for (int i = tid; i < QT * n4; i += 256) {
                const int r = i / n4;
                const int cc = (i - r * n4) << 2;
                *(float4*)&attn_out[base + (size_t)(q0 + r) * SS + zstart + cc] = z;
            }
        }
    }
}

// ---------------------------------------------------------------------------
extern "C" void kernel_launch(void* const* d_in, const int* in_sizes, int n_in,
                              void* d_out, int out_size)
{
    const float* Q  = (const float*)d_in[0];
    const float* K  = (const float*)d_in[1];
    const float* V  = (const float*)d_in[2];
    // d_in[3] = causal mask (fixed) — handled analytically
    const float* WQ = (const float*)d_in[4];
    const float* bQ = (const float*)d_in[5];
    const float* WK = (const float*)d_in[6];
    const float* bK = (const float*)d_in[7];
    const float* WV = (const float*)d_in[8];
    const float* bV = (const float*)d_in[9];
    const float* WO = (const float*)d_in[10];
    const float* bO = (const float*)d_in[11];

    __half *in0, *wh, *wl, *qh, *khh, *khl, *vth, *vtl, *ctx;
    cudaGetSymbolAddress((void**)&in0, g_in);
    cudaGetSymbolAddress((void**)&wh,  g_w_h);
    cudaGetSymbolAddress((void**)&wl,  g_w_l);
    cudaGetSymbolAddress((void**)&qh,  g_qh);
    cudaGetSymbolAddress((void**)&khh, g_kh_h);
    cudaGetSymbolAddress((void**)&khl, g_kh_l);
    cudaGetSymbolAddress((void**)&vth, g_vt_h);
    cudaGetSymbolAddress((void**)&vtl, g_vt_l);
    cudaGetSymbolAddress((void**)&ctx, g_ctx);

    float* out  = (float*)d_out;
    float* attn = out + OUT_ELEMS;
    const int write_attn =
        ((long long)out_size >= (long long)OUT_ELEMS + ATT_ELEMS) ? 1 : 0;

    cudaFuncSetAttribute(proj_gemm,
                         cudaFuncAttributeMaxDynamicSharedMemorySize, PROJ_SMEM);
    cudaFuncSetAttribute(attn_mma,
                         cudaFuncAttributeMaxDynamicSharedMemorySize, ATT_SMEM);

    convert_all<<<dim3(4096, 7), 256>>>(Q, K, V, WQ, WK, WV, WO);

    // fused Q/K/V projections
    proj_gemm<<<dim3(DD / 128, (BB * SS) / 128, 3), 256, PROJ_SMEM>>>(
        in0, in0 + 4194304, in0 + 2 * 4194304, ctx, wh, wl,
        bQ, bK, bV, bO, nullptr, qh, khh, khl, vth, vtl, -1);

    attn_mma<<<dim3(SS / QT, HH, BB), 256, ATT_SMEM>>>(
        qh, khh, khl, vth, vtl, ctx, attn, write_attn);

    // O projection
    proj_gemm<<<dim3(DD / 128, (BB * SS) / 128, 1), 256, PROJ_SMEM>>>(
        in0, in0 + 4194304, in0 + 2 * 4194304, ctx, wh, wl,
        bQ, bK, bV, bO, out, qh, khh, khl, vth, vtl, 3);
}